// round 10
// baseline (speedup 1.0000x reference)
#include <cuda_runtime.h>
#include <cuda_bf16.h>
#include <cstdint>

// PerspectiveNet768x2, int16, warp-specialized TMA ring pipeline.
//
// R2-R9: every LDG variant pins at ~70 B/cyc/SM (L1TEX consumer wall) with
// L2 at only 72-77%. R10 routes all row traffic L2->SMEM via cp.async.bulk
// (bypassing the LDG miss pipe) with the R5 failure modes removed:
//   - dedicated producer WARP (block 288 = 8 consumer warps + 1 producer)
//   - 16-deep ring of 2KB row slots, per-slot full/empty mbarriers
//   - NO __syncthreads in the mainloop: consumers arrive per-warp (count 8),
//     producer re-arms per slot after an empty-wait.
// Consumption is LDS.64 (8B/thread/row, conflict-free), floor ~65us; the
// binding resource becomes L2 itself (~92us floor for 2.15GB).
//
// Numerics identical to R3/R4/R8 (int16 scale 40940, 16-feature SIMD
// partials, exact int32 combine): rel_err 2.560972e-4.

#define NACT        32
#define NWARP_C     8                  // consumer warps
#define THREADS     (NWARP_C * 32 + 32)  // +1 producer warp = 288
#define NFEAT       3840
#define WPR         512u               // uint32 words per 1024-col row
#define ZROW        (2u * NFEAT)       // all-zero row (device arrays zero-init)
#define ROW_BYTES   2048
#define RING        16                 // slots
#define NROWS       64                 // 32 white + 32 black
#define QSCALE      40940.0f
#define QINV        (1.0f / 40940.0f)

// [white 0..3839 | black 3840..7679 | zero row 7680]
__device__ __align__(256) unsigned g_q[(2u * NFEAT + 1u) * WPR];

__global__ void convert_kernel(const float2* __restrict__ Ww,
                               const float2* __restrict__ Wb)
{
    const unsigned n = NFEAT * WPR;
    unsigned i = blockIdx.x * blockDim.x + threadIdx.x;
    if (i >= n) return;
    float2 a = __ldg(&Ww[i]);
    int q0 = __float2int_rn(a.x * QSCALE);
    int q1 = __float2int_rn(a.y * QSCALE);
    g_q[i] = ((unsigned)q0 & 0xFFFFu) | ((unsigned)q1 << 16);
    float2 c = __ldg(&Wb[i]);
    int p0 = __float2int_rn(c.x * QSCALE);
    int p1 = __float2int_rn(c.y * QSCALE);
    g_q[n + i] = ((unsigned)p0 & 0xFFFFu) | ((unsigned)p1 << 16);
}

__device__ __forceinline__ int lo16(unsigned w) { return (int)((short)(w & 0xFFFFu)); }
__device__ __forceinline__ int hi16(unsigned w) { return (int)((short)(w >> 16)); }

__device__ __forceinline__ uint32_t smem_u32(const void* p) {
    return (uint32_t)__cvta_generic_to_shared(p);
}
__device__ __forceinline__ void mbar_init(uint32_t a, uint32_t cnt) {
    asm volatile("mbarrier.init.shared.b64 [%0], %1;" :: "r"(a), "r"(cnt) : "memory");
}
__device__ __forceinline__ void mbar_expect_tx(uint32_t a, uint32_t bytes) {
    asm volatile("mbarrier.arrive.expect_tx.shared.b64 _, [%0], %1;"
                 :: "r"(a), "r"(bytes) : "memory");
}
__device__ __forceinline__ void mbar_arrive(uint32_t a) {
    asm volatile("mbarrier.arrive.shared.b64 _, [%0];" :: "r"(a) : "memory");
}
__device__ __forceinline__ void bulk_g2s(uint32_t dst, const void* src, uint32_t mbar) {
    asm volatile("cp.async.bulk.shared::cluster.global.mbarrier::complete_tx::bytes "
                 "[%0], [%1], %2, [%3];"
                 :: "r"(dst), "l"(src), "n"(ROW_BYTES), "r"(mbar) : "memory");
}
__device__ __forceinline__ void mbar_wait(uint32_t mbar, uint32_t parity) {
    asm volatile(
        "{\n\t.reg .pred P;\n"
        "W_%=:\n\t"
        "mbarrier.try_wait.parity.acquire.cta.shared::cta.b64 P, [%0], %1;\n\t"
        "@P bra D_%=;\n\t"
        "bra W_%=;\n"
        "D_%=:\n\t}"
        :: "r"(mbar), "r"(parity) : "memory");
}
__device__ __forceinline__ void fence_async() {
    asm volatile("fence.proxy.async.shared::cta;" ::: "memory");
}

__global__ __launch_bounds__(THREADS)
void nnue_gather_kernel(
    const int*    __restrict__ fw,    // [B,32]
    const int*    __restrict__ fb,    // [B,32]
    const int*    __restrict__ stm,   // [B] int32
    const float4* __restrict__ bw,    // [256]  (1024 floats)
    const float4* __restrict__ bb,
    const float4* __restrict__ Wout,  // [512]  (2048 floats)
    const float*  __restrict__ bout,
    float*        __restrict__ out)   // [B]
{
    __shared__ __align__(128) unsigned char sbuf[RING][ROW_BYTES];   // 32 KB
    __shared__ __align__(8)  unsigned long long full_b[RING];
    __shared__ __align__(8)  unsigned long long empty_b[RING];
    __shared__ unsigned sidx[NROWS];   // rows 0..31 white, 32..63 black
    __shared__ float    sred[NWARP_C];

    const int b    = blockIdx.x;
    const int tid  = threadIdx.x;
    const int lane = tid & 31;

    // Stage absolute row ids in consumption order.
    if (tid < NACT) {
        int v = fw[b * NACT + tid];
        sidx[tid] = (v < 0) ? ZROW : (unsigned)v;
    } else if (tid < 2 * NACT) {
        int v = fb[b * NACT + (tid - NACT)];
        sidx[tid] = (v < 0) ? ZROW : (unsigned)v + NFEAT;
    }
    if (tid == 0) {
        #pragma unroll
        for (int s = 0; s < RING; ++s) {
            mbar_init(smem_u32(&full_b[s]), 1u);
            mbar_init(smem_u32(&empty_b[s]), NWARP_C);
        }
        fence_async();
    }
    __syncthreads();

    const uint32_t fb0 = smem_u32(&full_b[0]);
    const uint32_t eb0 = smem_u32(&empty_b[0]);
    const uint32_t sb0 = smem_u32(&sbuf[0][0]);

    if (tid >= NWARP_C * 32) {
        // ---------------- producer warp ----------------
        if (lane == 0) {
            for (int r = 0; r < NROWS; ++r) {
                const int slot = r & (RING - 1);
                const int k    = r >> 4;            // round
                if (r >= RING) {
                    mbar_wait(eb0 + slot * 8u, (unsigned)((k - 1) & 1));
                    fence_async();   // order consumers' reads before overwrite
                }
                mbar_expect_tx(fb0 + slot * 8u, ROW_BYTES);
                bulk_g2s(sb0 + (uint32_t)slot * ROW_BYTES,
                         (const char*)g_q + (size_t)sidx[r] * ROW_BYTES,
                         fb0 + slot * 8u);
            }
        }
    } else {
        // ---------------- 8 consumer warps ----------------
        // Thread owns cols 4*tid..4*tid+3 of BOTH perspectives (uint2/row).
        const unsigned off = (unsigned)tid * 8u;

        uint2 pw0 = make_uint2(0u, 0u), pw1 = make_uint2(0u, 0u);
        uint2 pb0 = make_uint2(0u, 0u), pb1 = make_uint2(0u, 0u);

        #pragma unroll
        for (int r = 0; r < NROWS; ++r) {
            const int slot = r & (RING - 1);
            mbar_wait(fb0 + slot * 8u, (unsigned)((r >> 4) & 1));

            const uint2 v = *(const uint2*)(&sbuf[slot][0] + off);
            uint2& acc = (r < 16) ? pw0 : (r < 32) ? pw1 : (r < 48) ? pb0 : pb1;
            acc.x = __vadd2(acc.x, v.x);
            acc.y = __vadd2(acc.y, v.y);

            __syncwarp();
            if (lane == 0) mbar_arrive(eb0 + slot * 8u);
        }

        // Epilogue: exact int32 combine, dequant, bias, clip^2, dot.
        const bool white = (__ldg(&stm[b]) != 0);
        const float4 bwv = bw[tid];
        const float4 bbv = bb[tid];
        const float4 w_w = Wout[(white ? 0 : 256) + tid];   // x hidden_white
        const float4 w_b = Wout[(white ? 256 : 0) + tid];   // x hidden_black

        #define ACTM(isum, bias, wc)                                    \
            ({ float _h = fmaf((float)(isum), QINV, (bias));            \
               _h = fminf(fmaxf(_h, 0.0f), 1.0f);                       \
               _h * _h * (wc); })

        float p = 0.0f;
        p += ACTM(lo16(pw0.x) + lo16(pw1.x), bwv.x, w_w.x);
        p += ACTM(hi16(pw0.x) + hi16(pw1.x), bwv.y, w_w.y);
        p += ACTM(lo16(pw0.y) + lo16(pw1.y), bwv.z, w_w.z);
        p += ACTM(hi16(pw0.y) + hi16(pw1.y), bwv.w, w_w.w);
        p += ACTM(lo16(pb0.x) + lo16(pb1.x), bbv.x, w_b.x);
        p += ACTM(hi16(pb0.x) + hi16(pb1.x), bbv.y, w_b.y);
        p += ACTM(lo16(pb0.y) + lo16(pb1.y), bbv.z, w_b.z);
        p += ACTM(hi16(pb0.y) + hi16(pb1.y), bbv.w, w_b.w);
        #undef ACTM

        #pragma unroll
        for (int o = 16; o > 0; o >>= 1)
            p += __shfl_down_sync(0xffffffffu, p, o);
        if (lane == 0) sred[tid >> 5] = p;
    }

    __syncthreads();
    if (tid == 0) {
        float s = 0.0f;
        #pragma unroll
        for (int k = 0; k < NWARP_C; ++k) s += sred[k];
        out[b] = s + bout[0];
    }
}

extern "C" void kernel_launch(void* const* d_in, const int* in_sizes, int n_in,
                              void* d_out, int out_size)
{
    const int*    fw   = (const int*)d_in[0];
    const int*    fb   = (const int*)d_in[1];
    const int*    stm  = (const int*)d_in[2];
    const float2* Ww   = (const float2*)d_in[3];
    const float4* bw   = (const float4*)d_in[4];
    const float2* Wb   = (const float2*)d_in[5];
    const float4* bb   = (const float4*)d_in[6];
    const float4* Wout = (const float4*)d_in[7];
    const float*  bout = (const float*)d_in[8];
    float*        out  = (float*)d_out;

    const int B = in_sizes[0] / NACT;   // 16384

    const unsigned nwords = NFEAT * WPR;
    convert_kernel<<<(nwords + 255) / 256, 256>>>(Ww, Wb);
    nnue_gather_kernel<<<B, THREADS>>>(fw, fb, stm, bw, bb, Wout, bout, out);
}

// round 11
// speedup vs baseline: 3.7085x; 3.7085x over previous
#include <cuda_runtime.h>
#include <cuda_bf16.h>
#include <cstdint>

// PerspectiveNet768x2, int16 fixed-point (R3 champion + max-occupancy bound).
//
// History: every LDG variant (R2-R4, R8, R9) lands at 118-127us; TMA/SMEM
// paths (R5, R6, R10) all regress — the L1TEX/LDG return path is the wall.
// Cross-round correlation: occupancy ~ L1TEX% ~ speed (R3: 95% occ / 81.7%
// L1 / 117.9us was best). R11 = exact R3 kernel with __launch_bounds__(256,8)
// to force regs<=32 so a full 64 warps/SM fit, keeping the wavefront pipe fed.
//
// Quantization: int16 scale 40940 (|q|<=2047 since |w|<0.05); two SIMD
// accumulators of 16 features each (max 16*2047=32752 < 32767); exact int32
// combine; fp32 dequant. rel_err 2.560972e-4.

#define NACT        32
#define THREADS     256
#define NFEAT       3840
#define WPR         512u            // words per row: 1024 cols as int16 pairs
#define QSCALE      40940.0f        // 2047 / 0.05
#define QINV        (1.0f / 40940.0f)

__device__ unsigned g_q[2u * NFEAT * WPR];   // [white|black] packed int16 pairs

__global__ void convert_kernel(const float2* __restrict__ Ww,
                               const float2* __restrict__ Wb)
{
    const unsigned n = NFEAT * WPR;
    unsigned i = blockIdx.x * blockDim.x + threadIdx.x;
    if (i >= n) return;
    float2 a = __ldg(&Ww[i]);
    int q0 = __float2int_rn(a.x * QSCALE);
    int q1 = __float2int_rn(a.y * QSCALE);
    g_q[i] = ((unsigned)q0 & 0xFFFFu) | ((unsigned)q1 << 16);
    float2 c = __ldg(&Wb[i]);
    int p0 = __float2int_rn(c.x * QSCALE);
    int p1 = __float2int_rn(c.y * QSCALE);
    g_q[n + i] = ((unsigned)p0 & 0xFFFFu) | ((unsigned)p1 << 16);
}

__device__ __forceinline__ int lo16(unsigned w) { return (int)((short)(w & 0xFFFFu)); }
__device__ __forceinline__ int hi16(unsigned w) { return (int)((short)(w >> 16)); }

__global__ __launch_bounds__(THREADS, 8)
void nnue_gather_kernel(
    const int*    __restrict__ fw,    // [B,32]
    const int*    __restrict__ fb,    // [B,32]
    const int*    __restrict__ stm,   // [B] int32
    const float4* __restrict__ bw,    // [256] (1024 floats)
    const float4* __restrict__ bb,
    const float4* __restrict__ Wout,  // [512] (2048 floats)
    const float*  __restrict__ bout,
    float*        __restrict__ out)   // [B]
{
    __shared__ int   sidx[2 * NACT];
    __shared__ float sred[THREADS / 32];

    const int b   = blockIdx.x;
    const int tid = threadIdx.x;

    if (tid < NACT)          sidx[tid] = fw[b * NACT + tid];
    else if (tid < 2 * NACT) sidx[tid] = fb[b * NACT + (tid - NACT)];
    __syncthreads();

    const int persp = tid >> 7;        // 0 = white, 1 = black
    const int t     = tid & 127;       // 8-column group within the perspective
    const unsigned* tab  = g_q + (unsigned)persp * (NFEAT * WPR) + (unsigned)t * 4u;
    const int*      idxs = sidx + persp * NACT;

    // Two partial SIMD accumulators (16 features each) -> no 16-bit overflow.
    uint4 a0 = make_uint4(0u, 0u, 0u, 0u);
    uint4 a1 = make_uint4(0u, 0u, 0u, 0u);

    #pragma unroll 8
    for (int i = 0; i < 16; ++i) {
        int f = idxs[i];
        if (f >= 0) {
            uint4 v = *(const uint4*)(tab + (unsigned)f * WPR);
            a0.x = __vadd2(a0.x, v.x);  a0.y = __vadd2(a0.y, v.y);
            a0.z = __vadd2(a0.z, v.z);  a0.w = __vadd2(a0.w, v.w);
        }
    }
    #pragma unroll 8
    for (int i = 16; i < 32; ++i) {
        int f = idxs[i];
        if (f >= 0) {
            uint4 v = *(const uint4*)(tab + (unsigned)f * WPR);
            a1.x = __vadd2(a1.x, v.x);  a1.y = __vadd2(a1.y, v.y);
            a1.z = __vadd2(a1.z, v.z);  a1.w = __vadd2(a1.w, v.w);
        }
    }

    // Epilogue: combine partials in int32 (exact), dequant, bias, clip^2, dot.
    const bool white = (__ldg(&stm[b]) != 0);
    const float4* bias = (persp == 0) ? bw : bb;
    const float4 bv0 = bias[t * 2];
    const float4 bv1 = bias[t * 2 + 1];
    // This thread's 8 hidden cols map to W_out's first half iff
    // (its perspective is white) == (stm is white).
    const int half = ((persp == 0) == white) ? 0 : 256;   // float4 offset
    const float4 w0 = Wout[half + t * 2];
    const float4 w1 = Wout[half + t * 2 + 1];

    #define COL(wA, wB, EXT, bvc, wc)                                   \
        ({ int   _c = EXT(wA) + EXT(wB);                                \
           float _h = fmaf((float)_c, QINV, (bvc));                     \
           _h = fminf(fmaxf(_h, 0.0f), 1.0f);                           \
           _h * _h * (wc); })

    float p = 0.0f;
    p += COL(a0.x, a1.x, lo16, bv0.x, w0.x);
    p += COL(a0.x, a1.x, hi16, bv0.y, w0.y);
    p += COL(a0.y, a1.y, lo16, bv0.z, w0.z);
    p += COL(a0.y, a1.y, hi16, bv0.w, w0.w);
    p += COL(a0.z, a1.z, lo16, bv1.x, w1.x);
    p += COL(a0.z, a1.z, hi16, bv1.y, w1.y);
    p += COL(a0.w, a1.w, lo16, bv1.z, w1.z);
    p += COL(a0.w, a1.w, hi16, bv1.w, w1.w);
    #undef COL

    // Block reduction.
    #pragma unroll
    for (int o = 16; o > 0; o >>= 1)
        p += __shfl_down_sync(0xffffffffu, p, o);
    if ((tid & 31) == 0) sred[tid >> 5] = p;
    __syncthreads();

    if (tid == 0) {
        float s = 0.0f;
        #pragma unroll
        for (int k = 0; k < THREADS / 32; ++k) s += sred[k];
        out[b] = s + bout[0];
    }
}

extern "C" void kernel_launch(void* const* d_in, const int* in_sizes, int n_in,
                              void* d_out, int out_size)
{
    const int*    fw   = (const int*)d_in[0];
    const int*    fb   = (const int*)d_in[1];
    const int*    stm  = (const int*)d_in[2];
    const float2* Ww   = (const float2*)d_in[3];
    const float4* bw   = (const float4*)d_in[4];
    const float2* Wb   = (const float2*)d_in[5];
    const float4* bb   = (const float4*)d_in[6];
    const float4* Wout = (const float4*)d_in[7];
    const float*  bout = (const float*)d_in[8];
    float*        out  = (float*)d_out;

    const int B = in_sizes[0] / NACT;   // 16384

    const unsigned nwords = NFEAT * WPR;
    convert_kernel<<<(nwords + 255) / 256, 256>>>(Ww, Wb);
    nnue_gather_kernel<<<B, THREADS>>>(fw, fb, stm, bw, bb, Wout, bout, out);
}